// round 1
// baseline (speedup 1.0000x reference)
#include <cuda_runtime.h>
#include <cuda_bf16.h>

#define NNODES 100000
#define FEAT   128

// -------- scratch (static device globals; allocation-free per harness rules) ----
__device__ float g_self[NNODES * FEAT];   // feat @ W[0]
__device__ float g_msg [NNODES * FEAT];   // feat @ W[1]
__device__ float g_agg [NNODES * FEAT];   // segment-sum accumulator
__device__ float g_h   [NNODES * FEAT];   // hidden layer output
__device__ float g_invdeg[NNODES];        // 1/max(deg,1)

// ---------------------------------------------------------------- zero fill ----
__global__ void zero_kernel(float4* __restrict__ p, int n4) {
    int i = blockIdx.x * blockDim.x + threadIdx.x;
    if (i < n4) p[i] = make_float4(0.f, 0.f, 0.f, 0.f);
}

// ------------------------------------------------------------------- degree ----
__global__ void deg_kernel(const int* __restrict__ dst, int E) {
    int e = blockIdx.x * blockDim.x + threadIdx.x;
    if (e < E) atomicAdd(&g_invdeg[dst[e]], 1.0f);
}

__global__ void invdeg_kernel(int n) {
    int i = blockIdx.x * blockDim.x + threadIdx.x;
    if (i < n) g_invdeg[i] = 1.0f / fmaxf(g_invdeg[i], 1.0f);
}

// ------------------------------------------------------- fused dual GEMM -------
// out_self = feat @ Wa ; out_msg = feat @ Wb     (feat [nrows,128], W [128,128])
// Block: 256 threads (8 warps), 64 rows/block, 8 rows/warp.
// Weights (both) live in SMEM as Ws[k][n] with n in [0,256): cols 0..127 = Wa,
// 128..255 = Wb. Inner loop uses packed fma.rn.f32x2 for full-rate fp32.
#define TM 64
#define SMEM_W  (128 * 256)          // floats
#define SMEM_X  (TM * 128)           // floats
#define SMEM_GEMM_BYTES ((SMEM_W + SMEM_X) * 4)

__global__ __launch_bounds__(256, 1)
void dual_gemm_kernel(const float* __restrict__ feat,
                      const float* __restrict__ Wa,
                      const float* __restrict__ Wb,
                      float* __restrict__ out_self,
                      float* __restrict__ out_msg,
                      int nrows)
{
    extern __shared__ float sm[];
    float* Ws = sm;                 // [128][256]
    float* Xs = sm + SMEM_W;        // [TM][128]

    const int tid = threadIdx.x;

    // load both weight matrices (128*128 each) into combined SMEM tile
    #pragma unroll
    for (int i = tid; i < 128 * 128; i += 256) {
        int k = i >> 7, n = i & 127;
        Ws[k * 256 + n]       = Wa[i];
        Ws[k * 256 + n + 128] = Wb[i];
    }

    // load X tile (64 rows x 128 cols) as float4, zero-pad OOB rows
    const int row0 = blockIdx.x * TM;
    for (int i = tid; i < TM * 32; i += 256) {
        int r = i >> 5, c4 = i & 31;
        int row = row0 + r;
        float4 v = (row < nrows) ? ((const float4*)feat)[row * 32 + c4]
                                 : make_float4(0.f, 0.f, 0.f, 0.f);
        ((float4*)(Xs + r * 128))[c4] = v;
    }
    __syncthreads();

    const int warp = tid >> 5;
    const int lane = tid & 31;
    const int rbase = warp * 8;            // 8 rows per warp

    // accumulators: 8 rows x 4 column-pairs (f32x2 packed in u64)
    unsigned long long acc[8][4];
    #pragma unroll
    for (int r = 0; r < 8; ++r)
        #pragma unroll
        for (int c = 0; c < 4; ++c)
            acc[r][c] = 0ULL;

    const int colpair = 2 * lane;          // pair base column within 64-col group

    #pragma unroll 4
    for (int k = 0; k < 128; ++k) {
        unsigned long long wp[4];
        #pragma unroll
        for (int c = 0; c < 4; ++c)
            wp[c] = *(const unsigned long long*)(Ws + k * 256 + colpair + 64 * c);
        #pragma unroll
        for (int r = 0; r < 8; ++r) {
            unsigned int xb = __float_as_uint(Xs[(rbase + r) * 128 + k]);
            unsigned long long av;
            asm("mov.b64 %0, {%1, %1};" : "=l"(av) : "r"(xb));
            #pragma unroll
            for (int c = 0; c < 4; ++c)
                asm("fma.rn.f32x2 %0, %1, %2, %0;"
                    : "+l"(acc[r][c]) : "l"(av), "l"(wp[c]));
        }
    }

    // store: c=0,1 -> out_self cols [0,128), c=2,3 -> out_msg cols [0,128)
    #pragma unroll
    for (int r = 0; r < 8; ++r) {
        int row = row0 + rbase + r;
        if (row < nrows) {
            #pragma unroll
            for (int c = 0; c < 2; ++c)
                *(unsigned long long*)(out_self + row * 128 + colpair + 64 * c) = acc[r][c];
            #pragma unroll
            for (int c = 2; c < 4; ++c)
                *(unsigned long long*)(out_msg + row * 128 + colpair + 64 * (c - 2)) = acc[r][c];
        }
    }
}

// --------------------------------------------------- edge scatter (segment sum) ---
// One warp per edge: gather msg[src] (512B coalesced), vector-red into agg[dst].
__global__ void aggregate_kernel(const float* __restrict__ msg,
                                 const int* __restrict__ src,
                                 const int* __restrict__ dst,
                                 float* __restrict__ agg,
                                 int E)
{
    int widx = (blockIdx.x * blockDim.x + threadIdx.x) >> 5;
    int lane = threadIdx.x & 31;
    if (widx >= E) return;
    int s = __ldg(&src[widx]);
    int d = __ldg(&dst[widx]);
    float4 v = ((const float4*)msg)[s * 32 + lane];
    float4* addr = (float4*)(agg + d * 128 + lane * 4);
    asm volatile("red.global.add.v4.f32 [%0], {%1,%2,%3,%4};"
                 :: "l"(addr), "f"(v.x), "f"(v.y), "f"(v.z), "f"(v.w)
                 : "memory");
}

// ------------------------------------------------- combine: self + agg/deg -----
__global__ void combine_kernel(const float* __restrict__ self,
                               const float* __restrict__ agg,
                               float* __restrict__ out,
                               int n, int relu)
{
    int i = blockIdx.x * blockDim.x + threadIdx.x;   // over n*32 float4s
    if (i >= n * 32) return;
    int row = i >> 5;
    float inv = g_invdeg[row];
    float4 s = ((const float4*)self)[i];
    float4 a = ((const float4*)agg)[i];
    float4 o;
    o.x = fmaf(a.x, inv, s.x);
    o.y = fmaf(a.y, inv, s.y);
    o.z = fmaf(a.z, inv, s.z);
    o.w = fmaf(a.w, inv, s.w);
    if (relu) {
        o.x = fmaxf(o.x, 0.f); o.y = fmaxf(o.y, 0.f);
        o.z = fmaxf(o.z, 0.f); o.w = fmaxf(o.w, 0.f);
    }
    ((float4*)out)[i] = o;
}

// --------------------------------------------------------------------------------
extern "C" void kernel_launch(void* const* d_in, const int* in_sizes, int n_in,
                              void* d_out, int out_size)
{
    const float* x     = (const float*)d_in[0];
    const float* W_in  = (const float*)d_in[1];   // [2,128,128]
    const float* W_out = (const float*)d_in[2];   // [2,128,128]
    const int*   src   = (const int*)d_in[3];
    const int*   dst   = (const int*)d_in[4];
    float*       out   = (float*)d_out;

    const int N = in_sizes[0] / FEAT;
    const int E = in_sizes[3];

    float *p_self, *p_msg, *p_agg, *p_h, *p_invdeg;
    cudaGetSymbolAddress((void**)&p_self,   g_self);
    cudaGetSymbolAddress((void**)&p_msg,    g_msg);
    cudaGetSymbolAddress((void**)&p_agg,    g_agg);
    cudaGetSymbolAddress((void**)&p_h,      g_h);
    cudaGetSymbolAddress((void**)&p_invdeg, g_invdeg);

    static bool attr_set = false;
    if (!attr_set) {
        cudaFuncSetAttribute(dual_gemm_kernel,
                             cudaFuncAttributeMaxDynamicSharedMemorySize,
                             SMEM_GEMM_BYTES);
        attr_set = true;
    }

    const int nf4   = N * 32;                     // float4 count of [N,128]
    const int zgrid = (nf4 + 255) / 256;
    const int ggrid = (N + TM - 1) / TM;
    const int agrid = (E * 32 + 255) / 256;       // warp per edge
    const int cgrid = (nf4 + 255) / 256;

    // ---- degree (shared by both layers) ----
    zero_kernel<<<(N / 4 + 255) / 256, 256>>>((float4*)p_invdeg, N / 4);
    deg_kernel<<<(E + 255) / 256, 256>>>(dst, E);
    invdeg_kernel<<<(N + 255) / 256, 256>>>(N);

    // ---- layer 1: h = relu(x@W0 + mean_agg(x@W1)) ----
    dual_gemm_kernel<<<ggrid, 256, SMEM_GEMM_BYTES>>>(x, W_in, W_in + 128 * 128,
                                                      p_self, p_msg, N);
    zero_kernel<<<zgrid, 256>>>((float4*)p_agg, nf4);
    aggregate_kernel<<<agrid, 256>>>(p_msg, src, dst, p_agg, E);
    combine_kernel<<<cgrid, 256>>>(p_self, p_agg, p_h, N, 1);

    // ---- layer 2: out = h@W0' + mean_agg(h@W1') ----
    dual_gemm_kernel<<<ggrid, 256, SMEM_GEMM_BYTES>>>(p_h, W_out, W_out + 128 * 128,
                                                      p_self, p_msg, N);
    zero_kernel<<<zgrid, 256>>>((float4*)p_agg, nf4);
    aggregate_kernel<<<agrid, 256>>>(p_msg, src, dst, p_agg, E);
    combine_kernel<<<cgrid, 256>>>(p_self, p_agg, out, N, 0);
}

// round 2
// speedup vs baseline: 1.3159x; 1.3159x over previous
#include <cuda_runtime.h>
#include <cuda_bf16.h>

#define NNODES 100000
#define NEDGES 1600000
#define FEAT   128

// -------- scratch (static device globals; allocation-free per harness rules) ----
__device__ float g_self[NNODES * FEAT];   // feat @ W[0]
__device__ float g_msg [NNODES * FEAT];   // feat @ W[1]
__device__ float g_h   [NNODES * FEAT];   // hidden layer output
__device__ int   g_deg [NNODES];          // in-degree (int)
__device__ int   g_cursor[NNODES];        // CSR fill cursors
__device__ int   g_row_start[NNODES + 1]; // CSR row offsets
__device__ int   g_csr[NEDGES];           // CSR column (src) indices

// ------------------------------------------------------------- zero int fill ---
__global__ void zero_int2_kernel(int* __restrict__ a, int* __restrict__ b, int n) {
    int i = blockIdx.x * blockDim.x + threadIdx.x;
    if (i < n) { a[i] = 0; b[i] = 0; }
}

// ------------------------------------------------------------------- degree ----
__global__ void deg_kernel(const int* __restrict__ dst, int E) {
    int e = blockIdx.x * blockDim.x + threadIdx.x;
    if (e < E) atomicAdd(&g_deg[dst[e]], 1);
}

// ------------------------------------------ exclusive scan (single block) ------
__global__ void scan_kernel(int n) {
    __shared__ int part[1024];
    const int T = 1024;
    int tid = threadIdx.x;
    int chunk = (n + T - 1) / T;
    int b = tid * chunk;
    int e = min(b + chunk, n);
    int s = 0;
    for (int i = b; i < e; ++i) s += g_deg[i];
    part[tid] = s;
    __syncthreads();
    if (tid == 0) {
        int run = 0;
        for (int i = 0; i < T; ++i) { int t = part[i]; part[i] = run; run += t; }
    }
    __syncthreads();
    int run = part[tid];
    for (int i = b; i < e; ++i) { g_row_start[i] = run; run += g_deg[i]; }
    if (e == n) g_row_start[n] = run;
}

// ----------------------------------------------------------------- CSR fill ----
__global__ void fill_kernel(const int* __restrict__ src,
                            const int* __restrict__ dst, int E) {
    int e = blockIdx.x * blockDim.x + threadIdx.x;
    if (e < E) {
        int d = dst[e];
        int slot = g_row_start[d] + atomicAdd(&g_cursor[d], 1);
        g_csr[slot] = src[e];
    }
}

// ------------------------------------------------------- fused dual GEMM -------
// out_self = feat @ Wa ; out_msg = feat @ Wb     (feat [nrows,128], W [128,128])
// 512 threads (16 warps), 96 rows/block, 6 rows/warp. Both weights in SMEM as
// Ws[k][256] (cols 0..127 = Wa, 128..255 = Wb). Packed fma.rn.f32x2 inner loop.
#define TM 96
#define RPW 6
#define GEMM_THREADS 512
#define SMEM_W  (128 * 256)          // floats
#define SMEM_X  (TM * 128)           // floats
#define SMEM_GEMM_BYTES ((SMEM_W + SMEM_X) * 4)

__global__ __launch_bounds__(GEMM_THREADS, 1)
void dual_gemm_kernel(const float* __restrict__ feat,
                      const float* __restrict__ Wa,
                      const float* __restrict__ Wb,
                      float* __restrict__ out_self,
                      float* __restrict__ out_msg,
                      int nrows)
{
    extern __shared__ float sm[];
    float* Ws = sm;                 // [128][256]
    float* Xs = sm + SMEM_W;        // [TM][128]

    const int tid = threadIdx.x;

    // load both weight matrices into combined SMEM tile
    #pragma unroll
    for (int i = tid; i < 128 * 128; i += GEMM_THREADS) {
        int k = i >> 7, n = i & 127;
        Ws[k * 256 + n]       = Wa[i];
        Ws[k * 256 + n + 128] = Wb[i];
    }

    // load X tile (96 rows x 128 cols) as float4, zero-pad OOB rows
    const int row0 = blockIdx.x * TM;
    for (int i = tid; i < TM * 32; i += GEMM_THREADS) {
        int r = i >> 5, c4 = i & 31;
        int row = row0 + r;
        float4 v = (row < nrows) ? ((const float4*)feat)[row * 32 + c4]
                                 : make_float4(0.f, 0.f, 0.f, 0.f);
        ((float4*)(Xs + r * 128))[c4] = v;
    }
    __syncthreads();

    const int warp = tid >> 5;
    const int lane = tid & 31;
    const int rbase = warp * RPW;

    // accumulators: 6 rows x 4 column-pairs (f32x2 packed in u64)
    unsigned long long acc[RPW][4];
    #pragma unroll
    for (int r = 0; r < RPW; ++r)
        #pragma unroll
        for (int c = 0; c < 4; ++c)
            acc[r][c] = 0ULL;

    const int colpair = 2 * lane;

    #pragma unroll 4
    for (int k = 0; k < 128; ++k) {
        unsigned long long wp[4];
        #pragma unroll
        for (int c = 0; c < 4; ++c)
            wp[c] = *(const unsigned long long*)(Ws + k * 256 + colpair + 64 * c);
        #pragma unroll
        for (int r = 0; r < RPW; ++r) {
            unsigned int xb = __float_as_uint(Xs[(rbase + r) * 128 + k]);
            unsigned long long av;
            asm("mov.b64 %0, {%1, %1};" : "=l"(av) : "r"(xb));
            #pragma unroll
            for (int c = 0; c < 4; ++c)
                asm("fma.rn.f32x2 %0, %1, %2, %0;"
                    : "+l"(acc[r][c]) : "l"(av), "l"(wp[c]));
        }
    }

    // store: c=0,1 -> out_self, c=2,3 -> out_msg
    #pragma unroll
    for (int r = 0; r < RPW; ++r) {
        int row = row0 + rbase + r;
        if (row < nrows) {
            #pragma unroll
            for (int c = 0; c < 2; ++c)
                *(unsigned long long*)(out_self + row * 128 + colpair + 64 * c) = acc[r][c];
            #pragma unroll
            for (int c = 2; c < 4; ++c)
                *(unsigned long long*)(out_msg + row * 128 + colpair + 64 * (c - 2)) = acc[r][c];
        }
    }
}

// ------------------------- CSR gather-mean + combine (+ReLU), warp per dst -----
__global__ void agg_csr_kernel(const float* __restrict__ msg,
                               const float* __restrict__ self,
                               float* __restrict__ out,
                               int N, int relu)
{
    int w = (blockIdx.x * blockDim.x + threadIdx.x) >> 5;
    if (w >= N) return;
    int lane = threadIdx.x & 31;

    int beg = g_row_start[w];
    int end = g_row_start[w + 1];

    float4 a0 = make_float4(0.f, 0.f, 0.f, 0.f);
    float4 a1 = make_float4(0.f, 0.f, 0.f, 0.f);

    int e = beg;
    for (; e + 2 <= end; e += 2) {
        int s0 = g_csr[e];
        int s1 = g_csr[e + 1];
        float4 v0 = __ldg(&((const float4*)msg)[s0 * 32 + lane]);
        float4 v1 = __ldg(&((const float4*)msg)[s1 * 32 + lane]);
        a0.x += v0.x; a0.y += v0.y; a0.z += v0.z; a0.w += v0.w;
        a1.x += v1.x; a1.y += v1.y; a1.z += v1.z; a1.w += v1.w;
    }
    if (e < end) {
        int s0 = g_csr[e];
        float4 v0 = __ldg(&((const float4*)msg)[s0 * 32 + lane]);
        a0.x += v0.x; a0.y += v0.y; a0.z += v0.z; a0.w += v0.w;
    }

    float inv = 1.0f / fmaxf((float)(end - beg), 1.0f);
    float4 sf = ((const float4*)self)[w * 32 + lane];
    float4 o;
    o.x = fmaf(a0.x + a1.x, inv, sf.x);
    o.y = fmaf(a0.y + a1.y, inv, sf.y);
    o.z = fmaf(a0.z + a1.z, inv, sf.z);
    o.w = fmaf(a0.w + a1.w, inv, sf.w);
    if (relu) {
        o.x = fmaxf(o.x, 0.f); o.y = fmaxf(o.y, 0.f);
        o.z = fmaxf(o.z, 0.f); o.w = fmaxf(o.w, 0.f);
    }
    ((float4*)out)[w * 32 + lane] = o;
}

// --------------------------------------------------------------------------------
extern "C" void kernel_launch(void* const* d_in, const int* in_sizes, int n_in,
                              void* d_out, int out_size)
{
    const float* x     = (const float*)d_in[0];
    const float* W_in  = (const float*)d_in[1];   // [2,128,128]
    const float* W_out = (const float*)d_in[2];   // [2,128,128]
    const int*   src   = (const int*)d_in[3];
    const int*   dst   = (const int*)d_in[4];
    float*       out   = (float*)d_out;

    const int N = in_sizes[0] / FEAT;
    const int E = in_sizes[3];

    float *p_self, *p_msg, *p_h;
    int *p_deg, *p_cursor;
    cudaGetSymbolAddress((void**)&p_self,   g_self);
    cudaGetSymbolAddress((void**)&p_msg,    g_msg);
    cudaGetSymbolAddress((void**)&p_h,      g_h);
    cudaGetSymbolAddress((void**)&p_deg,    g_deg);
    cudaGetSymbolAddress((void**)&p_cursor, g_cursor);

    static bool attr_set = false;
    if (!attr_set) {
        cudaFuncSetAttribute(dual_gemm_kernel,
                             cudaFuncAttributeMaxDynamicSharedMemorySize,
                             SMEM_GEMM_BYTES);
        attr_set = true;
    }

    const int ggrid = (N + TM - 1) / TM;
    const int agrid = (N * 32 + 255) / 256;       // warp per dst node
    const int egrid = (E + 255) / 256;

    // ---- CSR build (graph shared by both layers) ----
    zero_int2_kernel<<<(N + 255) / 256, 256>>>(p_deg, p_cursor, N);
    deg_kernel<<<egrid, 256>>>(dst, E);
    scan_kernel<<<1, 1024>>>(N);
    fill_kernel<<<egrid, 256>>>(src, dst, E);

    // ---- layer 1: h = relu(x@W0 + mean_agg(x@W1)) ----
    dual_gemm_kernel<<<ggrid, GEMM_THREADS, SMEM_GEMM_BYTES>>>(
        x, W_in, W_in + 128 * 128, p_self, p_msg, N);
    agg_csr_kernel<<<agrid, 256>>>(p_msg, p_self, p_h, N, 1);

    // ---- layer 2: out = h@W0' + mean_agg(h@W1') ----
    dual_gemm_kernel<<<ggrid, GEMM_THREADS, SMEM_GEMM_BYTES>>>(
        p_h, W_out, W_out + 128 * 128, p_self, p_msg, N);
    agg_csr_kernel<<<agrid, 256>>>(p_msg, p_self, out, N, 0);
}

// round 4
// speedup vs baseline: 1.8321x; 1.3923x over previous
#include <cuda_runtime.h>
#include <cuda_bf16.h>
#include <cstdint>

#define NNODES 100000
#define NEDGES 1600000
#define FEAT   128

// -------- scratch (static device globals; allocation-free per harness rules) ----
__device__ __align__(16) float g_self[NNODES * FEAT];
__device__ __align__(16) float g_msg [NNODES * FEAT];
__device__ __align__(16) float g_h   [NNODES * FEAT];
__device__ int   g_deg [NNODES];
__device__ int   g_row_start[NNODES + 1];
__device__ int   g_csr[NEDGES];
// bf16 split weights, pre-transposed to [layer][n(0..255)][k(0..127)]
__device__ __align__(16) __nv_bfloat16 g_B0[2 * 256 * 128];
__device__ __align__(16) __nv_bfloat16 g_B1[2 * 256 * 128];

// ================================ helpers =======================================
__device__ __forceinline__ uint32_t sm_u32(const void* p) {
    uint32_t a;
    asm("{ .reg .u64 t; cvta.to.shared.u64 t, %1; cvt.u32.u64 %0, t; }"
        : "=r"(a) : "l"(p));
    return a;
}
__device__ __forceinline__ void ldsm_x4(uint32_t* r, uint32_t addr) {
    asm volatile("ldmatrix.sync.aligned.m8n8.x4.shared.b16 {%0,%1,%2,%3}, [%4];"
                 : "=r"(r[0]), "=r"(r[1]), "=r"(r[2]), "=r"(r[3]) : "r"(addr));
}
__device__ __forceinline__ void mma16816(float* c, const uint32_t* a,
                                         uint32_t b0, uint32_t b1) {
    asm volatile("mma.sync.aligned.m16n8k16.row.col.f32.bf16.bf16.f32 "
                 "{%0,%1,%2,%3}, {%4,%5,%6,%7}, {%8,%9}, {%0,%1,%2,%3};"
                 : "+f"(c[0]), "+f"(c[1]), "+f"(c[2]), "+f"(c[3])
                 : "r"(a[0]), "r"(a[1]), "r"(a[2]), "r"(a[3]), "r"(b0), "r"(b1));
}
__device__ __forceinline__ uint32_t pack_bf2(float a, float b) {
    __nv_bfloat162 h = __floats2bfloat162_rn(a, b);
    return *(uint32_t*)&h;
}

// ============================= weight prep (once) ===============================
// g_B*[layer][n][k]: n<128 -> W[0] col n ; n>=128 -> W[1] col n-128 ; transposed.
__global__ void wprep_kernel(const float* __restrict__ W_in,
                             const float* __restrict__ W_out) {
    int idx = blockIdx.x * blockDim.x + threadIdx.x;
    if (idx >= 2 * 256 * 128) return;
    int layer = idx >> 15;
    int n = (idx >> 7) & 255;
    int k = idx & 127;
    const float* W = (layer ? W_out : W_in) + ((n >= 128) ? 128 * 128 : 0);
    float w = W[k * 128 + (n & 127)];
    __nv_bfloat16 w0 = __float2bfloat16(w);
    __nv_bfloat16 w1 = __float2bfloat16(w - __bfloat162float(w0));
    g_B0[idx] = w0;
    g_B1[idx] = w1;
}

// =============================== CSR build ======================================
__global__ void zero_int_kernel(int* __restrict__ a, int n) {
    int i = blockIdx.x * blockDim.x + threadIdx.x;
    if (i < n) a[i] = 0;
}
__global__ void deg_kernel(const int* __restrict__ dst, int E) {
    int e = blockIdx.x * blockDim.x + threadIdx.x;
    if (e < E) atomicAdd(&g_deg[dst[e]], 1);
}
__global__ void scan_kernel(int n) {
    __shared__ int part[1024];
    const int T = 1024;
    int tid = threadIdx.x;
    int chunk = (n + T - 1) / T;
    int b = tid * chunk, e = min(b + chunk, n);
    int s = 0;
    for (int i = b; i < e; ++i) s += g_deg[i];
    part[tid] = s;
    __syncthreads();
    if (tid == 0) {
        int run = 0;
        for (int i = 0; i < T; ++i) { int t = part[i]; part[i] = run; run += t; }
    }
    __syncthreads();
    int run = part[tid];
    for (int i = b; i < e; ++i) { g_row_start[i] = run; run += g_deg[i]; }
    if (e == n) g_row_start[n] = run;
}
__global__ void fill_kernel(const int* __restrict__ src,
                            const int* __restrict__ dst, int E) {
    int e = blockIdx.x * blockDim.x + threadIdx.x;
    if (e < E) {
        int d = dst[e];
        int slot = g_row_start[d] + atomicSub(&g_deg[d], 1) - 1;
        g_csr[slot] = src[e];
    }
}

// ================= mma.sync dual GEMM (split-bf16, 3 chains) ====================
// D[128][256] = X[128,128] @ [Wa | Wb];  D = Ahi*Bhi + Ahi*Blo + Alo*Bhi (fp32 acc)
// SMEM (bf16, rows 256B, 16B-chunk XOR swizzle): Ahi @0, Alo @32K, Bhi @64K, Blo @128K
#define GT 512
#define SM_AHI 0
#define SM_ALO 32768
#define SM_BHI 65536
#define SM_BLO 131072
#define SMEM_TOTAL_GEMM 196608

__global__ __launch_bounds__(GT, 1)
void mma_gemm_kernel(const float* __restrict__ feat,
                     const __nv_bfloat16* __restrict__ Bg0,
                     const __nv_bfloat16* __restrict__ Bg1,
                     float* __restrict__ out_self,
                     float* __restrict__ out_msg,
                     int nrows)
{
    extern __shared__ char smc[];
    const int tid = threadIdx.x;
    const uint32_t sb = sm_u32(smc);
    const int row0 = blockIdx.x * 128;

    // ---- B tiles: 256 rows x 16 chunks of 16B, swizzled
    for (int i = tid; i < 4096; i += GT) {
        int n = i >> 4, ch = i & 15;
        uint4 v0 = *(const uint4*)(Bg0 + n * 128 + ch * 8);
        uint4 v1 = *(const uint4*)(Bg1 + n * 128 + ch * 8);
        uint32_t off = n * 256 + ((ch ^ (n & 7)) << 4);
        *(uint4*)(smc + SM_BHI + off) = v0;
        *(uint4*)(smc + SM_BLO + off) = v1;
    }
    // ---- A tile: 128 rows x 16 chunks; split fp32 -> bf16 hi/lo
    for (int i = tid; i < 2048; i += GT) {
        int r = i >> 4, ch = i & 15;
        int row = row0 + r;
        float4 u = make_float4(0.f, 0.f, 0.f, 0.f), v = u;
        if (row < nrows) {
            u = ((const float4*)feat)[row * 32 + ch * 2];
            v = ((const float4*)feat)[row * 32 + ch * 2 + 1];
        }
        float xs[8] = {u.x, u.y, u.z, u.w, v.x, v.y, v.z, v.w};
        float hi[8];
        #pragma unroll
        for (int j = 0; j < 8; ++j)
            hi[j] = __bfloat162float(__float2bfloat16(xs[j]));
        uint4 h4, l4;
        h4.x = pack_bf2(hi[0], hi[1]);            h4.y = pack_bf2(hi[2], hi[3]);
        h4.z = pack_bf2(hi[4], hi[5]);            h4.w = pack_bf2(hi[6], hi[7]);
        l4.x = pack_bf2(xs[0]-hi[0], xs[1]-hi[1]); l4.y = pack_bf2(xs[2]-hi[2], xs[3]-hi[3]);
        l4.z = pack_bf2(xs[4]-hi[4], xs[5]-hi[5]); l4.w = pack_bf2(xs[6]-hi[6], xs[7]-hi[7]);
        uint32_t off = r * 256 + ((ch ^ (r & 7)) << 4);
        *(uint4*)(smc + SM_AHI + off) = h4;
        *(uint4*)(smc + SM_ALO + off) = l4;
    }
    __syncthreads();

    const int wid = tid >> 5, lane = tid & 31;
    const int mw = wid & 3;          // M block: 32 rows
    const int nw = wid >> 2;         // N block: 64 cols
    const int s3 = lane & 7, sel = lane >> 3;

    float acc[2][8][4];
    #pragma unroll
    for (int a = 0; a < 2; ++a)
        #pragma unroll
        for (int b = 0; b < 8; ++b)
            #pragma unroll
            for (int c = 0; c < 4; ++c) acc[a][b][c] = 0.f;

    #pragma unroll
    for (int ks = 0; ks < 8; ++ks) {
        uint32_t ahi[2][4], alo[2][4];
        #pragma unroll
        for (int mt = 0; mt < 2; ++mt) {
            int r = mw * 32 + mt * 16 + s3 + ((sel & 1) << 3);
            int ch = 2 * ks + (sel >> 1);
            uint32_t off = r * 256 + ((ch ^ (r & 7)) << 4);
            ldsm_x4(ahi[mt], sb + SM_AHI + off);
            ldsm_x4(alo[mt], sb + SM_ALO + off);
        }
        #pragma unroll
        for (int jp = 0; jp < 4; ++jp) {     // pairs of n8-tiles
            int r = nw * 64 + jp * 16 + s3 + ((sel >> 1) << 3);
            int ch = 2 * ks + (sel & 1);
            uint32_t off = r * 256 + ((ch ^ (r & 7)) << 4);
            uint32_t bhi[4], blo[4];
            ldsm_x4(bhi, sb + SM_BHI + off);
            ldsm_x4(blo, sb + SM_BLO + off);
            #pragma unroll
            for (int t = 0; t < 2; ++t) {
                int nt = jp * 2 + t;
                #pragma unroll
                for (int mt = 0; mt < 2; ++mt) {
                    mma16816(acc[mt][nt], ahi[mt], bhi[2*t], bhi[2*t+1]);
                    mma16816(acc[mt][nt], ahi[mt], blo[2*t], blo[2*t+1]);
                    mma16816(acc[mt][nt], alo[mt], bhi[2*t], bhi[2*t+1]);
                }
            }
        }
    }

    // ---- epilogue: nw 0,1 -> out_self cols 0..127 ; nw 2,3 -> out_msg
    const int g = lane >> 2, tq = lane & 3;
    float* dstb = (nw < 2) ? out_self : out_msg;
    const int colhalf = (nw & 1) * 64;
    #pragma unroll
    for (int mt = 0; mt < 2; ++mt) {
        int rr = row0 + mw * 32 + mt * 16 + g;
        #pragma unroll
        for (int nt = 0; nt < 8; ++nt) {
            int col = colhalf + nt * 8 + 2 * tq;
            if (rr < nrows)
                *(float2*)(dstb + (size_t)rr * 128 + col) =
                    make_float2(acc[mt][nt][0], acc[mt][nt][1]);
            if (rr + 8 < nrows)
                *(float2*)(dstb + (size_t)(rr + 8) * 128 + col) =
                    make_float2(acc[mt][nt][2], acc[mt][nt][3]);
        }
    }
}

// ------------------------- CSR gather-mean + combine (+ReLU) -------------------
__global__ void agg_csr_kernel(const float* __restrict__ msg,
                               const float* __restrict__ self,
                               float* __restrict__ out,
                               int N, int relu)
{
    int w = (blockIdx.x * blockDim.x + threadIdx.x) >> 5;
    if (w >= N) return;
    int lane = threadIdx.x & 31;

    int beg = g_row_start[w];
    int end = g_row_start[w + 1];

    float4 a0 = make_float4(0.f, 0.f, 0.f, 0.f);
    float4 a1 = make_float4(0.f, 0.f, 0.f, 0.f);

    int e = beg;
    for (; e + 2 <= end; e += 2) {
        int s0 = g_csr[e];
        int s1 = g_csr[e + 1];
        float4 v0 = __ldg(&((const float4*)msg)[s0 * 32 + lane]);
        float4 v1 = __ldg(&((const float4*)msg)[s1 * 32 + lane]);
        a0.x += v0.x; a0.y += v0.y; a0.z += v0.z; a0.w += v0.w;
        a1.x += v1.x; a1.y += v1.y; a1.z += v1.z; a1.w += v1.w;
    }
    if (e < end) {
        int s0 = g_csr[e];
        float4 v0 = __ldg(&((const float4*)msg)[s0 * 32 + lane]);
        a0.x += v0.x; a0.y += v0.y; a0.z += v0.z; a0.w += v0.w;
    }

    float inv = 1.0f / fmaxf((float)(end - beg), 1.0f);
    float4 sf = ((const float4*)self)[w * 32 + lane];
    float4 o;
    o.x = fmaf(a0.x + a1.x, inv, sf.x);
    o.y = fmaf(a0.y + a1.y, inv, sf.y);
    o.z = fmaf(a0.z + a1.z, inv, sf.z);
    o.w = fmaf(a0.w + a1.w, inv, sf.w);
    if (relu) {
        o.x = fmaxf(o.x, 0.f); o.y = fmaxf(o.y, 0.f);
        o.z = fmaxf(o.z, 0.f); o.w = fmaxf(o.w, 0.f);
    }
    ((float4*)out)[w * 32 + lane] = o;
}

// --------------------------------------------------------------------------------
extern "C" void kernel_launch(void* const* d_in, const int* in_sizes, int n_in,
                              void* d_out, int out_size)
{
    const float* x     = (const float*)d_in[0];
    const float* W_in  = (const float*)d_in[1];
    const float* W_out = (const float*)d_in[2];
    const int*   src   = (const int*)d_in[3];
    const int*   dst   = (const int*)d_in[4];
    float*       out   = (float*)d_out;

    const int N = in_sizes[0] / FEAT;
    const int E = in_sizes[3];

    float *p_self, *p_msg, *p_h;
    int *p_deg;
    __nv_bfloat16 *p_B0, *p_B1;
    cudaGetSymbolAddress((void**)&p_self, g_self);
    cudaGetSymbolAddress((void**)&p_msg,  g_msg);
    cudaGetSymbolAddress((void**)&p_h,    g_h);
    cudaGetSymbolAddress((void**)&p_deg,  g_deg);
    cudaGetSymbolAddress((void**)&p_B0,   g_B0);
    cudaGetSymbolAddress((void**)&p_B1,   g_B1);

    static bool attr_set = false;
    if (!attr_set) {
        cudaFuncSetAttribute(mma_gemm_kernel,
                             cudaFuncAttributeMaxDynamicSharedMemorySize,
                             SMEM_TOTAL_GEMM);
        attr_set = true;
    }

    const int ggrid = (N + 127) / 128;
    const int agrid = (N * 32 + 255) / 256;
    const int egrid = (E + 255) / 256;

    // ---- one-time prep: CSR + weights ----
    zero_int_kernel<<<(N + 255) / 256, 256>>>(p_deg, N);
    deg_kernel<<<egrid, 256>>>(dst, E);
    scan_kernel<<<1, 1024>>>(N);
    fill_kernel<<<egrid, 256>>>(src, dst, E);
    wprep_kernel<<<(2 * 256 * 128 + 255) / 256, 256>>>(W_in, W_out);

    // ---- layer 1: h = relu(x@W0 + mean_agg(x@W1)) ----
    mma_gemm_kernel<<<ggrid, GT, SMEM_TOTAL_GEMM>>>(
        x, p_B0, p_B1, p_self, p_msg, N);
    agg_csr_kernel<<<agrid, 256>>>(p_msg, p_self, p_h, N, 1);

    // ---- layer 2: out = h@W0' + mean_agg(h@W1') ----
    mma_gemm_kernel<<<ggrid, GT, SMEM_TOTAL_GEMM>>>(
        p_h, p_B0 + 256 * 128, p_B1 + 256 * 128, p_self, p_msg, N);
    agg_csr_kernel<<<agrid, 256>>>(p_msg, p_self, out, N, 0);
}

// round 5
// speedup vs baseline: 2.1432x; 1.1698x over previous
#include <cuda_runtime.h>
#include <cuda_bf16.h>
#include <cuda_fp16.h>
#include <cstdint>

#define NNODES 100000
#define NEDGES 1600000
#define FEAT   128

// -------- scratch (static device globals; allocation-free per harness rules) ----
__device__ __align__(16) float  g_self[NNODES * FEAT];
__device__ __align__(16) __half g_msg [NNODES * FEAT];   // fp16: only feeds mean-agg
__device__ __align__(16) float  g_h   [NNODES * FEAT];
__device__ int   g_deg [NNODES];
__device__ int   g_row_start[NNODES + 1];
__device__ int   g_csr[NEDGES];
// bf16 split weights, pre-transposed to [layer][n(0..255)][k(0..127)]
__device__ __align__(16) __nv_bfloat16 g_B0[2 * 256 * 128];
__device__ __align__(16) __nv_bfloat16 g_B1[2 * 256 * 128];

// ================================ helpers =======================================
__device__ __forceinline__ uint32_t sm_u32(const void* p) {
    uint32_t a;
    asm("{ .reg .u64 t; cvta.to.shared.u64 t, %1; cvt.u32.u64 %0, t; }"
        : "=r"(a) : "l"(p));
    return a;
}
__device__ __forceinline__ void ldsm_x4(uint32_t* r, uint32_t addr) {
    asm volatile("ldmatrix.sync.aligned.m8n8.x4.shared.b16 {%0,%1,%2,%3}, [%4];"
                 : "=r"(r[0]), "=r"(r[1]), "=r"(r[2]), "=r"(r[3]) : "r"(addr));
}
__device__ __forceinline__ void mma16816(float* c, const uint32_t* a,
                                         uint32_t b0, uint32_t b1) {
    asm volatile("mma.sync.aligned.m16n8k16.row.col.f32.bf16.bf16.f32 "
                 "{%0,%1,%2,%3}, {%4,%5,%6,%7}, {%8,%9}, {%0,%1,%2,%3};"
                 : "+f"(c[0]), "+f"(c[1]), "+f"(c[2]), "+f"(c[3])
                 : "r"(a[0]), "r"(a[1]), "r"(a[2]), "r"(a[3]), "r"(b0), "r"(b1));
}
__device__ __forceinline__ uint32_t pack_bf2(float a, float b) {
    __nv_bfloat162 h = __floats2bfloat162_rn(a, b);
    return *(uint32_t*)&h;
}

// ============================= weight prep (once) ===============================
__global__ void wprep_kernel(const float* __restrict__ W_in,
                             const float* __restrict__ W_out) {
    int idx = blockIdx.x * blockDim.x + threadIdx.x;
    if (idx >= 2 * 256 * 128) return;
    int layer = idx >> 15;
    int n = (idx >> 7) & 255;
    int k = idx & 127;
    const float* W = (layer ? W_out : W_in) + ((n >= 128) ? 128 * 128 : 0);
    float w = W[k * 128 + (n & 127)];
    __nv_bfloat16 w0 = __float2bfloat16(w);
    __nv_bfloat16 w1 = __float2bfloat16(w - __bfloat162float(w0));
    g_B0[idx] = w0;
    g_B1[idx] = w1;
}

// =============================== CSR build ======================================
__global__ void zero_int_kernel(int* __restrict__ a, int n) {
    int i = blockIdx.x * blockDim.x + threadIdx.x;
    if (i < n) a[i] = 0;
}
__global__ void deg_kernel(const int* __restrict__ dst, int E) {
    int e = blockIdx.x * blockDim.x + threadIdx.x;
    if (e < E) atomicAdd(&g_deg[dst[e]], 1);
}
__global__ void scan_kernel(int n) {
    __shared__ int part[1024];
    const int T = 1024;
    int tid = threadIdx.x;
    int chunk = (n + T - 1) / T;
    int b = tid * chunk, e = min(b + chunk, n);
    int s = 0;
    for (int i = b; i < e; ++i) s += g_deg[i];
    part[tid] = s;
    __syncthreads();
    if (tid == 0) {
        int run = 0;
        for (int i = 0; i < T; ++i) { int t = part[i]; part[i] = run; run += t; }
    }
    __syncthreads();
    int run = part[tid];
    for (int i = b; i < e; ++i) { g_row_start[i] = run; run += g_deg[i]; }
    if (e == n) g_row_start[n] = run;
}
__global__ void fill_kernel(const int* __restrict__ src,
                            const int* __restrict__ dst, int E) {
    int e = blockIdx.x * blockDim.x + threadIdx.x;
    if (e < E) {
        int d = dst[e];
        int slot = g_row_start[d] + atomicSub(&g_deg[d], 1) - 1;
        g_csr[slot] = src[e];
    }
}

// ================= mma.sync dual GEMM (split-bf16, 3 chains) ====================
// D[128][256] = X[128,128] @ [Wa | Wb];  D = Ahi*Bhi + Ahi*Blo + Alo*Bhi (fp32 acc)
// out_self: fp32 ; out_msg: fp16 (agg-only consumer)
#define GT 512
#define SM_AHI 0
#define SM_ALO 32768
#define SM_BHI 65536
#define SM_BLO 131072
#define SMEM_TOTAL_GEMM 196608

__global__ __launch_bounds__(GT, 1)
void mma_gemm_kernel(const float* __restrict__ feat,
                     const __nv_bfloat16* __restrict__ Bg0,
                     const __nv_bfloat16* __restrict__ Bg1,
                     float* __restrict__ out_self,
                     __half* __restrict__ out_msg,
                     int nrows)
{
    extern __shared__ char smc[];
    const int tid = threadIdx.x;
    const uint32_t sb = sm_u32(smc);
    const int row0 = blockIdx.x * 128;

    // ---- B tiles: 256 rows x 16 chunks of 16B, swizzled
    for (int i = tid; i < 4096; i += GT) {
        int n = i >> 4, ch = i & 15;
        uint4 v0 = *(const uint4*)(Bg0 + n * 128 + ch * 8);
        uint4 v1 = *(const uint4*)(Bg1 + n * 128 + ch * 8);
        uint32_t off = n * 256 + ((ch ^ (n & 7)) << 4);
        *(uint4*)(smc + SM_BHI + off) = v0;
        *(uint4*)(smc + SM_BLO + off) = v1;
    }
    // ---- A tile: 128 rows x 16 chunks; split fp32 -> bf16 hi/lo
    for (int i = tid; i < 2048; i += GT) {
        int r = i >> 4, ch = i & 15;
        int row = row0 + r;
        float4 u = make_float4(0.f, 0.f, 0.f, 0.f), v = u;
        if (row < nrows) {
            u = ((const float4*)feat)[row * 32 + ch * 2];
            v = ((const float4*)feat)[row * 32 + ch * 2 + 1];
        }
        float xs[8] = {u.x, u.y, u.z, u.w, v.x, v.y, v.z, v.w};
        float hi[8];
        #pragma unroll
        for (int j = 0; j < 8; ++j)
            hi[j] = __bfloat162float(__float2bfloat16(xs[j]));
        uint4 h4, l4;
        h4.x = pack_bf2(hi[0], hi[1]);            h4.y = pack_bf2(hi[2], hi[3]);
        h4.z = pack_bf2(hi[4], hi[5]);            h4.w = pack_bf2(hi[6], hi[7]);
        l4.x = pack_bf2(xs[0]-hi[0], xs[1]-hi[1]); l4.y = pack_bf2(xs[2]-hi[2], xs[3]-hi[3]);
        l4.z = pack_bf2(xs[4]-hi[4], xs[5]-hi[5]); l4.w = pack_bf2(xs[6]-hi[6], xs[7]-hi[7]);
        uint32_t off = r * 256 + ((ch ^ (r & 7)) << 4);
        *(uint4*)(smc + SM_AHI + off) = h4;
        *(uint4*)(smc + SM_ALO + off) = l4;
    }
    __syncthreads();

    const int wid = tid >> 5, lane = tid & 31;
    const int mw = wid & 3;          // M block: 32 rows
    const int nw = wid >> 2;         // N block: 64 cols
    const int s3 = lane & 7, sel = lane >> 3;

    float acc[2][8][4];
    #pragma unroll
    for (int a = 0; a < 2; ++a)
        #pragma unroll
        for (int b = 0; b < 8; ++b)
            #pragma unroll
            for (int c = 0; c < 4; ++c) acc[a][b][c] = 0.f;

    #pragma unroll
    for (int ks = 0; ks < 8; ++ks) {
        uint32_t ahi[2][4], alo[2][4];
        #pragma unroll
        for (int mt = 0; mt < 2; ++mt) {
            int r = mw * 32 + mt * 16 + s3 + ((sel & 1) << 3);
            int ch = 2 * ks + (sel >> 1);
            uint32_t off = r * 256 + ((ch ^ (r & 7)) << 4);
            ldsm_x4(ahi[mt], sb + SM_AHI + off);
            ldsm_x4(alo[mt], sb + SM_ALO + off);
        }
        #pragma unroll
        for (int jp = 0; jp < 4; ++jp) {
            int r = nw * 64 + jp * 16 + s3 + ((sel >> 1) << 3);
            int ch = 2 * ks + (sel & 1);
            uint32_t off = r * 256 + ((ch ^ (r & 7)) << 4);
            uint32_t bhi[4], blo[4];
            ldsm_x4(bhi, sb + SM_BHI + off);
            ldsm_x4(blo, sb + SM_BLO + off);
            #pragma unroll
            for (int t = 0; t < 2; ++t) {
                int nt = jp * 2 + t;
                #pragma unroll
                for (int mt = 0; mt < 2; ++mt) {
                    mma16816(acc[mt][nt], ahi[mt], bhi[2*t], bhi[2*t+1]);
                    mma16816(acc[mt][nt], ahi[mt], blo[2*t], blo[2*t+1]);
                    mma16816(acc[mt][nt], alo[mt], bhi[2*t], bhi[2*t+1]);
                }
            }
        }
    }

    // ---- epilogue: nw 0,1 -> out_self (fp32) ; nw 2,3 -> out_msg (fp16)
    const int g = lane >> 2, tq = lane & 3;
    const int colhalf = (nw & 1) * 64;
    #pragma unroll
    for (int mt = 0; mt < 2; ++mt) {
        int rr = row0 + mw * 32 + mt * 16 + g;
        #pragma unroll
        for (int nt = 0; nt < 8; ++nt) {
            int col = colhalf + nt * 8 + 2 * tq;
            if (nw < 2) {
                if (rr < nrows)
                    *(float2*)(out_self + (size_t)rr * 128 + col) =
                        make_float2(acc[mt][nt][0], acc[mt][nt][1]);
                if (rr + 8 < nrows)
                    *(float2*)(out_self + (size_t)(rr + 8) * 128 + col) =
                        make_float2(acc[mt][nt][2], acc[mt][nt][3]);
            } else {
                if (rr < nrows)
                    *(__half2*)(out_msg + (size_t)rr * 128 + col) =
                        __floats2half2_rn(acc[mt][nt][0], acc[mt][nt][1]);
                if (rr + 8 < nrows)
                    *(__half2*)(out_msg + (size_t)(rr + 8) * 128 + col) =
                        __floats2half2_rn(acc[mt][nt][2], acc[mt][nt][3]);
            }
        }
    }
}

// ------------------- CSR gather-mean (fp16 msg) + combine (+ReLU) ---------------
__global__ void agg_csr_kernel(const __half* __restrict__ msg,
                               const float* __restrict__ self,
                               float* __restrict__ out,
                               int N, int relu)
{
    int w = (blockIdx.x * blockDim.x + threadIdx.x) >> 5;
    if (w >= N) return;
    int lane = threadIdx.x & 31;

    int beg = g_row_start[w];
    int end = g_row_start[w + 1];

    float4 a0 = make_float4(0.f, 0.f, 0.f, 0.f);
    float4 a1 = make_float4(0.f, 0.f, 0.f, 0.f);

    int e = beg;
    for (; e + 2 <= end; e += 2) {
        int s0 = g_csr[e];
        int s1 = g_csr[e + 1];
        uint2 u0 = __ldg((const uint2*)(msg + (size_t)s0 * 128) + lane);
        uint2 u1 = __ldg((const uint2*)(msg + (size_t)s1 * 128) + lane);
        float2 f00 = __half22float2(*(__half2*)&u0.x);
        float2 f01 = __half22float2(*(__half2*)&u0.y);
        float2 f10 = __half22float2(*(__half2*)&u1.x);
        float2 f11 = __half22float2(*(__half2*)&u1.y);
        a0.x += f00.x; a0.y += f00.y; a0.z += f01.x; a0.w += f01.y;
        a1.x += f10.x; a1.y += f10.y; a1.z += f11.x; a1.w += f11.y;
    }
    if (e < end) {
        int s0 = g_csr[e];
        uint2 u0 = __ldg((const uint2*)(msg + (size_t)s0 * 128) + lane);
        float2 f00 = __half22float2(*(__half2*)&u0.x);
        float2 f01 = __half22float2(*(__half2*)&u0.y);
        a0.x += f00.x; a0.y += f00.y; a0.z += f01.x; a0.w += f01.y;
    }

    float inv = 1.0f / fmaxf((float)(end - beg), 1.0f);
    float4 sf = ((const float4*)self)[w * 32 + lane];
    float4 o;
    o.x = fmaf(a0.x + a1.x, inv, sf.x);
    o.y = fmaf(a0.y + a1.y, inv, sf.y);
    o.z = fmaf(a0.z + a1.z, inv, sf.z);
    o.w = fmaf(a0.w + a1.w, inv, sf.w);
    if (relu) {
        o.x = fmaxf(o.x, 0.f); o.y = fmaxf(o.y, 0.f);
        o.z = fmaxf(o.z, 0.f); o.w = fmaxf(o.w, 0.f);
    }
    ((float4*)out)[w * 32 + lane] = o;
}

// --------------------------------------------------------------------------------
extern "C" void kernel_launch(void* const* d_in, const int* in_sizes, int n_in,
                              void* d_out, int out_size)
{
    const float* x     = (const float*)d_in[0];
    const float* W_in  = (const float*)d_in[1];
    const float* W_out = (const float*)d_in[2];
    const int*   src   = (const int*)d_in[3];
    const int*   dst   = (const int*)d_in[4];
    float*       out   = (float*)d_out;

    const int N = in_sizes[0] / FEAT;
    const int E = in_sizes[3];

    float *p_self, *p_h;
    __half *p_msg;
    int *p_deg;
    __nv_bfloat16 *p_B0, *p_B1;
    cudaGetSymbolAddress((void**)&p_self, g_self);
    cudaGetSymbolAddress((void**)&p_msg,  g_msg);
    cudaGetSymbolAddress((void**)&p_h,    g_h);
    cudaGetSymbolAddress((void**)&p_deg,  g_deg);
    cudaGetSymbolAddress((void**)&p_B0,   g_B0);
    cudaGetSymbolAddress((void**)&p_B1,   g_B1);

    static bool s_init = false;
    static cudaStream_t s2 = 0;
    static cudaEvent_t evF = 0, evJ = 0;
    if (!s_init) {
        cudaFuncSetAttribute(mma_gemm_kernel,
                             cudaFuncAttributeMaxDynamicSharedMemorySize,
                             SMEM_TOTAL_GEMM);
        if (cudaStreamCreateWithFlags(&s2, cudaStreamNonBlocking) != cudaSuccess)
            s2 = 0;
        cudaEventCreateWithFlags(&evF, cudaEventDisableTiming);
        cudaEventCreateWithFlags(&evJ, cudaEventDisableTiming);
        s_init = true;
    }

    const int ggrid = (N + 127) / 128;
    const int agrid = (N * 32 + 255) / 256;
    const int egrid = (E + 255) / 256;

    // ---- fork: CSR build on side stream, overlapped with wprep + layer-1 GEMM ----
    cudaEventRecord(evF, 0);
    cudaStreamWaitEvent(s2, evF, 0);
    zero_int_kernel<<<(N + 255) / 256, 256, 0, s2>>>(p_deg, N);
    deg_kernel<<<egrid, 256, 0, s2>>>(dst, E);
    scan_kernel<<<1, 1024, 0, s2>>>(N);
    fill_kernel<<<egrid, 256, 0, s2>>>(src, dst, E);
    cudaEventRecord(evJ, s2);

    wprep_kernel<<<(2 * 256 * 128 + 255) / 256, 256>>>(W_in, W_out);
    mma_gemm_kernel<<<ggrid, GT, SMEM_TOTAL_GEMM>>>(
        x, p_B0, p_B1, p_self, p_msg, N);

    // ---- join: aggregation needs the CSR ----
    cudaStreamWaitEvent(0, evJ, 0);
    agg_csr_kernel<<<agrid, 256>>>(p_msg, p_self, p_h, N, 1);

    // ---- layer 2 ----
    mma_gemm_kernel<<<ggrid, GT, SMEM_TOTAL_GEMM>>>(
        p_h, p_B0 + 256 * 128, p_B1 + 256 * 128, p_self, p_msg, N);
    agg_csr_kernel<<<agrid, 256>>>(p_msg, p_self, out, N, 0);
}